// round 3
// baseline (speedup 1.0000x reference)
#include <cuda_runtime.h>
#include <cuda_bf16.h>

// Problem constants (fixed by the bench instance)
#define VSZ    32128
#define V4SZ   8032         // VSZ / 4
#define RIDX   512
#define LTOT   520
#define KD     8            // K = L - r
#define NROW   9            // softmax rows 511..519
#define NCH    16           // chunks per row for the parallel reduction
#define CH4    502          // V4SZ / NCH
#define GRIDN  1184         // 148 SMs x 8 blocks -> exactly one wave
#define TAILB  32           // last 32 blocks handle the 8 tail rows (4 each)
#define TOT4   (RIDX * V4SZ)   // flat float4 count of the probs copy

// Scratch (no cudaMalloc allowed). Zero-initialized at module load; the
// kernel self-resets all counters/flags at the end of every launch so
// graph replays see a clean state.
__device__ float g_pm[NROW][NCH];
__device__ float g_ps[NROW][NCH];
__device__ int   g_pa[NROW][NCH];
__device__ float g_m[NROW];
__device__ float g_s[NROW];
__device__ int   g_amax[NROW];
__device__ int   g_nmatch;
__device__ int   g_cntA;     // completed A-partial blocks
__device__ int   g_flag;     // stats ready
__device__ int   g_done;     // completed blocks (for cleanup)

__global__ __launch_bounds__(256, 8)
void fused(const float* __restrict__ logits,
           const float* __restrict__ probs,
           const void*  __restrict__ idsv,
           float* __restrict__ out, int out_size)
{
    const int blk = blockIdx.x;
    const int tid = threadIdx.x;

    // =======================================================================
    // Phase A: blocks 0..143 compute softmax partials (row j, chunk ch).
    // The last one to finish runs the combine + accept chain (phase B).
    // =======================================================================
    if (blk < NROW * NCH) {
        const int j  = blk >> 4;       // 0..8 -> logits row 511+j
        const int ch = blk & 15;       // 0..15
        const float4* row = (const float4*)(logits + (size_t)(511 + j) * VSZ) + ch * CH4;

        float bm = -3.402823466e38f;
        int   bi = 0x7fffffff;
        float s  = 0.f;
        for (int c = tid; c < CH4; c += 256) {
            float4 v = row[c];
            int base = 4 * (ch * CH4 + c);
            if (v.x > bm) { s *= __expf(bm - v.x); s += 1.f; bm = v.x; bi = base;     } else s += __expf(v.x - bm);
            if (v.y > bm) { s *= __expf(bm - v.y); s += 1.f; bm = v.y; bi = base + 1; } else s += __expf(v.y - bm);
            if (v.z > bm) { s *= __expf(bm - v.z); s += 1.f; bm = v.z; bi = base + 2; } else s += __expf(v.z - bm);
            if (v.w > bm) { s *= __expf(bm - v.w); s += 1.f; bm = v.w; bi = base + 3; } else s += __expf(v.w - bm);
        }
        __shared__ float sm[256], ss[256];
        __shared__ int   si[256];
        __shared__ int   s_last;
        sm[tid] = bm; si[tid] = bi; ss[tid] = s;
        __syncthreads();
        for (int off = 128; off > 0; off >>= 1) {
            if (tid < off) {
                float om = sm[tid + off]; int oi = si[tid + off]; float os = ss[tid + off];
                float mm = sm[tid];       int mi = si[tid];       float ms = ss[tid];
                float M  = fmaxf(om, mm);
                ss[tid] = ms * __expf(mm - M) + os * __expf(om - M);
                if (om > mm || (om == mm && oi < mi)) { sm[tid] = om; si[tid] = oi; }
            }
            __syncthreads();
        }
        if (tid == 0) {
            g_pm[j][ch] = sm[0]; g_ps[j][ch] = ss[0]; g_pa[j][ch] = si[0];
            __threadfence();
            int r = atomicAdd(&g_cntA, 1);
            s_last = (r == NROW * NCH - 1);
        }
        __syncthreads();

        if (s_last) {
            // ---- Phase B (runs in exactly one block) ----
            __threadfence();  // acquire partials
            __shared__ int s_nz;
            __shared__ int s_acc[KD];
            __shared__ int s_d[KD];
            if (tid == 0) s_nz = 0;

            if (tid < NROW) {
                float M = -3.402823466e38f;
                int   A = 0;
                #pragma unroll
                for (int c = 0; c < NCH; c++) {
                    float pm = g_pm[tid][c];
                    if (pm > M) { M = pm; A = g_pa[tid][c]; }
                }
                float S = 0.f;
                #pragma unroll
                for (int c = 0; c < NCH; c++)
                    S += g_ps[tid][c] * __expf(g_pm[tid][c] - M);
                g_m[tid] = M; g_s[tid] = S; g_amax[tid] = A;
            }
            __syncthreads();

            // dtype probe: int64 nonneg ids => all odd 32-bit words zero.
            const int* w = (const int*)idsv;
            for (int i = 1 + 2 * tid; i < LTOT; i += 2 * 256)
                if (w[i] != 0) s_nz = 1;   // benign race
            __syncthreads();
            const bool is64 = (s_nz == 0);
            const long long* w64 = (const long long*)idsv;

            // id_res[0:512] = input_ids[0:512]
            for (int i = tid; i < RIDX; i += 256) {
                int idv = is64 ? (int)w64[i] : w[i];
                out[i] = (float)idv;
            }

            if (tid < KD) {
                int d = is64 ? (int)w64[RIDX + tid] : w[RIDX + tid];
                s_d[tid] = d;
                float tp = __expf(logits[(size_t)(511 + tid) * VSZ + d] - g_m[tid]) / g_s[tid];
                float pp = probs[(size_t)(511 + tid) * VSZ + d];
                int eq      = (g_amax[tid] == d);
                int lenient = (tp > pp * 0.5f);    // leniency = 2
                s_acc[tid] = eq | lenient;
            }
            __syncthreads();

            if (tid == 0) {
                int nm = 0;
                for (int j2 = 0; j2 < KD; j2++) { if (s_acc[j2]) nm++; else break; }
                for (int pos = 0; pos <= KD; pos++) {
                    float v;
                    if (pos < nm)       v = (float)s_d[pos];
                    else if (pos == nm) v = (float)g_amax[pos];
                    else                v = 0.f;
                    out[RIDX + pos] = v;
                }
                out[out_size - 1] = (float)nm;
                g_nmatch = nm;
                __threadfence();
                atomicExch(&g_flag, 1);      // release stats for tail blocks
            }
        }
    }

    // =======================================================================
    // Phase C0: flat copy prob_res rows 0..511. out[521+e] = probs[e].
    // Grid-stride over all GRIDN blocks (coalesced float4 loads).
    // =======================================================================
    {
        const float4* p4 = (const float4*)probs;
        float* ob = out + 521;
        for (size_t i = (size_t)blk * 256 + tid; i < (size_t)TOT4; i += (size_t)GRIDN * 256) {
            float4 v = p4[i];
            float* o = ob + 4 * i;
            o[0] = v.x; o[1] = v.y; o[2] = v.z; o[3] = v.w;
        }
    }

    // =======================================================================
    // Phase C1: last TAILB blocks emit the 8 tail rows (need n_match/stats).
    // =======================================================================
    if (blk >= GRIDN - TAILB) {
        const int t    = blk - (GRIDN - TAILB);   // 0..31
        const int j    = t >> 2;                  // tail row 0..7
        const int part = t & 3;                   // quarter of the row
        if (j < KD) {
            while (atomicAdd(&g_flag, 0) == 0) __nanosleep(64);
            __threadfence();
            const int nm = g_nmatch;
            float* orow = out + 521 + (size_t)(RIDX + j) * VSZ;
            const int cbeg = part * (V4SZ / 4);
            const int cend = cbeg + (V4SZ / 4);
            if (j < nm) {
                const float M   = g_m[j];
                const float inv = 1.0f / g_s[j];
                const float4* p = (const float4*)(logits + (size_t)(511 + j) * VSZ);
                for (int c = cbeg + tid; c < cend; c += 256) {
                    float4 v = p[c];
                    float* o = orow + 4 * c;
                    o[0] = __expf(v.x - M) * inv;
                    o[1] = __expf(v.y - M) * inv;
                    o[2] = __expf(v.z - M) * inv;
                    o[3] = __expf(v.w - M) * inv;
                }
            } else {
                for (int c = cbeg + tid; c < cend; c += 256) {
                    float* o = orow + 4 * c;
                    o[0] = 0.f; o[1] = 0.f; o[2] = 0.f; o[3] = 0.f;
                }
            }
        }
    }

    // =======================================================================
    // Cleanup: last block to finish resets all state for the next replay.
    // =======================================================================
    if (tid == 0) {
        int d = atomicAdd(&g_done, 1);
        if (d == GRIDN - 1) {
            g_cntA = 0;
            g_flag = 0;
            g_done = 0;
            __threadfence();
        }
    }
}

// ---------------------------------------------------------------------------
extern "C" void kernel_launch(void* const* d_in, const int* in_sizes, int n_in,
                              void* d_out, int out_size) {
    const float* logits = (const float*)d_in[0];   // target_logits f32 (1,520,32128)
    const float* probs  = (const float*)d_in[1];   // probs         f32 (1,520,32128)
    const void*  ids    = d_in[2];                 // input_ids int32/int64 (1,520)
    float* out = (float*)d_out;

    fused<<<GRIDN, 256>>>(logits, probs, ids, out, out_size);
}